// round 3
// baseline (speedup 1.0000x reference)
#include <cuda_runtime.h>
#include <cstdint>
#include <math.h>

#define HID    2048
#define NHEADS 16
#define HDIM   128
#define SEQ    2048
#define BATCH  2
#define MROWS  (BATCH*SEQ)   // 4096

// ---------------- scratch (static device globals; no allocations allowed) ----
__device__ float g_q  [(size_t)MROWS * HID];
__device__ float g_k  [(size_t)MROWS * HID];
__device__ float g_v  [(size_t)MROWS * HID];
__device__ float g_ctx[(size_t)MROWS * HID];

// ---------------- GEMM: C[M,N] = A[M,K] @ W[N,K]^T + bias[N] (+ res) --------
// M = MROWS, N = K = HID (compile-time).
// a_sel: 0 -> use Ain, 1 -> g_ctx.  c_sel: 0 -> Cout, 1/2/3 -> g_q/g_k/g_v.
#define BM 128
#define BN 128
#define BK 32

__global__ __launch_bounds__(256)
void gemm_tn(const float* __restrict__ Ain, const float* __restrict__ W,
             const float* __restrict__ bias, const float* __restrict__ res,
             float* __restrict__ Cout, int a_sel, int c_sel)
{
    const float* A = (a_sel == 1) ? g_ctx : Ain;
    float*       C = (c_sel == 1) ? g_q
                   : (c_sel == 2) ? g_k
                   : (c_sel == 3) ? g_v : Cout;

    __shared__ float As[BK][BM + 4];
    __shared__ float Ws[BK][BN + 4];

    const int tid = threadIdx.x;
    const int bm  = blockIdx.y * BM;
    const int bn  = blockIdx.x * BN;
    const int ty  = tid >> 4;        // 0..15
    const int tx  = tid & 15;        // 0..15

    float acc[8][8];
#pragma unroll
    for (int i = 0; i < 8; i++)
#pragma unroll
        for (int j = 0; j < 8; j++) acc[i][j] = 0.f;

    const int lr = tid >> 3;         // 0..31 (row within 32-row slab)
    const int lc = (tid & 7) * 4;    // 0,4,...,28 (k offset, float4)

    for (int kt = 0; kt < HID; kt += BK) {
        __syncthreads();
#pragma unroll
        for (int rr = 0; rr < BM; rr += 32) {
            float4 va = *(const float4*)(A + (size_t)(bm + lr + rr) * HID + kt + lc);
            As[lc + 0][lr + rr] = va.x;
            As[lc + 1][lr + rr] = va.y;
            As[lc + 2][lr + rr] = va.z;
            As[lc + 3][lr + rr] = va.w;
            float4 vw = *(const float4*)(W + (size_t)(bn + lr + rr) * HID + kt + lc);
            Ws[lc + 0][lr + rr] = vw.x;
            Ws[lc + 1][lr + rr] = vw.y;
            Ws[lc + 2][lr + rr] = vw.z;
            Ws[lc + 3][lr + rr] = vw.w;
        }
        __syncthreads();

#pragma unroll
        for (int kk = 0; kk < BK; kk++) {
            float a[8], b[8];
#pragma unroll
            for (int i = 0; i < 8; i++) a[i] = As[kk][ty * 8 + i];
#pragma unroll
            for (int j = 0; j < 8; j++) b[j] = Ws[kk][tx * 8 + j];
#pragma unroll
            for (int i = 0; i < 8; i++)
#pragma unroll
                for (int j = 0; j < 8; j++)
                    acc[i][j] = fmaf(a[i], b[j], acc[i][j]);
        }
    }

    if (res) {
#pragma unroll
        for (int i = 0; i < 8; i++) {
            const int r = bm + ty * 8 + i;
#pragma unroll
            for (int j = 0; j < 8; j++) {
                const int c = bn + tx * 8 + j;
                C[(size_t)r * HID + c] = acc[i][j] + bias[c] + res[(size_t)r * HID + c];
            }
        }
    } else {
#pragma unroll
        for (int i = 0; i < 8; i++) {
            const int r = bm + ty * 8 + i;
#pragma unroll
            for (int j = 0; j < 8; j++) {
                const int c = bn + tx * 8 + j;
                C[(size_t)r * HID + c] = acc[i][j] + bias[c];
            }
        }
    }
}

// ---------------- Flash attention ------------------------------------------
// grid: (SEQ/AQ, NHEADS, BATCH), 256 threads.
// Reads g_q/g_k/g_v ([B,S,H], feature = h*HDIM + d), writes g_ctx.
#define AQ 64
#define AK 64
#define KPAD (AK + 4)    // 68

#define ATTN_SMEM_FLOATS (AQ*HDIM + HDIM*KPAD + AK*HDIM + AQ*KPAD)
#define ATTN_SMEM_BYTES  (ATTN_SMEM_FLOATS * 4)

__global__ __launch_bounds__(256)
void flash_attn(const float* __restrict__ alibi)
{
    extern __shared__ float sm[];
    float* qs  = sm;                      // [AQ][HDIM]
    float* kst = qs  + AQ * HDIM;         // [HDIM][KPAD]  (K transposed)
    float* vs  = kst + HDIM * KPAD;       // [AK][HDIM]
    float* ps  = vs  + AK * HDIM;         // [AQ][KPAD]

    const int qb  = blockIdx.x;           // q tile
    const int h   = blockIdx.y;
    const int b   = blockIdx.z;
    const int tid = threadIdx.x;
    const int ty  = tid >> 4;             // 0..15
    const int tx  = tid & 15;             // 0..15

    const float inv_norm = 0.08838834764831844f;  // 1/sqrt(128)

    // load Q tile: rows qb*AQ .. +63, features h*HDIM..+127
    for (int i = tid; i < AQ * (HDIM / 4); i += 256) {
        const int r  = i / (HDIM / 4);
        const int c4 = (i % (HDIM / 4)) * 4;
        float4 v = *(const float4*)(g_q + (size_t)(b * SEQ + qb * AQ + r) * HID + h * HDIM + c4);
        *(float4*)(qs + r * HDIM + c4) = v;
    }

    float m[4], l[4];
    float acc[4][8];
#pragma unroll
    for (int i = 0; i < 4; i++) { m[i] = -INFINITY; l[i] = 0.f; }
#pragma unroll
    for (int i = 0; i < 4; i++)
#pragma unroll
        for (int j = 0; j < 8; j++) acc[i][j] = 0.f;

    const float* al = alibi + (size_t)(b * NHEADS + h) * SEQ;

    for (int kt = 0; kt < SEQ; kt += AK) {
        __syncthreads();   // previous iteration done with kst/vs/ps
        // load K tile transposed: kst[d][r]
        for (int i = tid; i < AK * (HDIM / 4); i += 256) {
            const int r  = i / (HDIM / 4);
            const int c4 = (i % (HDIM / 4)) * 4;
            float4 v = *(const float4*)(g_k + (size_t)(b * SEQ + kt + r) * HID + h * HDIM + c4);
            kst[(c4 + 0) * KPAD + r] = v.x;
            kst[(c4 + 1) * KPAD + r] = v.y;
            kst[(c4 + 2) * KPAD + r] = v.z;
            kst[(c4 + 3) * KPAD + r] = v.w;
        }
        // load V tile: vs[r][d]
        for (int i = tid; i < AK * (HDIM / 4); i += 256) {
            const int r  = i / (HDIM / 4);
            const int c4 = (i % (HDIM / 4)) * 4;
            float4 v = *(const float4*)(g_v + (size_t)(b * SEQ + kt + r) * HID + h * HDIM + c4);
            *(float4*)(vs + r * HDIM + c4) = v;
        }
        __syncthreads();

        // scores: s[i][j] for rows ty*4+i, cols tx*4+j
        float s[4][4];
#pragma unroll
        for (int i = 0; i < 4; i++)
#pragma unroll
            for (int j = 0; j < 4; j++) s[i][j] = 0.f;

#pragma unroll 4
        for (int kk = 0; kk < HDIM; kk++) {
            float a[4], bb[4];
#pragma unroll
            for (int i = 0; i < 4; i++) a[i]  = qs[(ty * 4 + i) * HDIM + kk];
#pragma unroll
            for (int j = 0; j < 4; j++) bb[j] = kst[kk * KPAD + tx * 4 + j];
#pragma unroll
            for (int i = 0; i < 4; i++)
#pragma unroll
                for (int j = 0; j < 4; j++)
                    s[i][j] = fmaf(a[i], bb[j], s[i][j]);
        }

        float alv[4];
#pragma unroll
        for (int j = 0; j < 4; j++) alv[j] = al[kt + tx * 4 + j];
#pragma unroll
        for (int i = 0; i < 4; i++)
#pragma unroll
            for (int j = 0; j < 4; j++)
                s[i][j] = s[i][j] * inv_norm + alv[j];

        // online softmax per row (row team = 16 lanes of same ty, one shfl segment)
        float rowscale[4];
#pragma unroll
        for (int i = 0; i < 4; i++) {
            float rm = s[i][0];
#pragma unroll
            for (int j = 1; j < 4; j++) rm = fmaxf(rm, s[i][j]);
#pragma unroll
            for (int off = 8; off >= 1; off >>= 1)
                rm = fmaxf(rm, __shfl_xor_sync(0xffffffffu, rm, off, 16));
            const float mnew = fmaxf(m[i], rm);
            rowscale[i] = __expf(m[i] - mnew);
            float rs = 0.f;
#pragma unroll
            for (int j = 0; j < 4; j++) {
                const float p = __expf(s[i][j] - mnew);
                s[i][j] = p;
                rs += p;
            }
#pragma unroll
            for (int off = 8; off >= 1; off >>= 1)
                rs += __shfl_xor_sync(0xffffffffu, rs, off, 16);
            l[i] = l[i] * rowscale[i] + rs;
            m[i] = mnew;
        }

        // stage probs
#pragma unroll
        for (int i = 0; i < 4; i++)
#pragma unroll
            for (int j = 0; j < 4; j++)
                ps[(ty * 4 + i) * KPAD + tx * 4 + j] = s[i][j];
        __syncthreads();

        // ctx accumulate: rows ty*4+i, cols tx*8+j
#pragma unroll
        for (int i = 0; i < 4; i++)
#pragma unroll
            for (int j = 0; j < 8; j++) acc[i][j] *= rowscale[i];

#pragma unroll 4
        for (int c = 0; c < AK; c++) {
            float pv[4], vv[8];
#pragma unroll
            for (int i = 0; i < 4; i++) pv[i] = ps[(ty * 4 + i) * KPAD + c];
#pragma unroll
            for (int j = 0; j < 8; j++) vv[j] = vs[c * HDIM + tx * 8 + j];
#pragma unroll
            for (int i = 0; i < 4; i++)
#pragma unroll
                for (int j = 0; j < 8; j++)
                    acc[i][j] = fmaf(pv[i], vv[j], acc[i][j]);
        }
    }

    // epilogue: ctx[(b,S,q), h*HDIM + d], normalized by l
#pragma unroll
    for (int i = 0; i < 4; i++) {
        const float inv_l = 1.0f / l[i];
        const size_t base = (size_t)(b * SEQ + qb * AQ + ty * 4 + i) * HID + h * HDIM + tx * 8;
#pragma unroll
        for (int j = 0; j < 8; j++)
            g_ctx[base + j] = acc[i][j] * inv_l;
    }
}

// ---------------- launch ----------------------------------------------------
extern "C" void kernel_launch(void* const* d_in, const int* in_sizes, int n_in,
                              void* d_out, int out_size)
{
    const float* x     = (const float*)d_in[0];
    const float* resid = (const float*)d_in[1];
    const float* alibi = (const float*)d_in[2];
    const float* Wq    = (const float*)d_in[3];
    const float* bq    = (const float*)d_in[4];
    const float* Wk    = (const float*)d_in[5];
    const float* bk    = (const float*)d_in[6];
    const float* Wv    = (const float*)d_in[7];
    const float* bv    = (const float*)d_in[8];
    const float* Wd    = (const float*)d_in[9];
    const float* bd    = (const float*)d_in[10];
    float* out = (float*)d_out;

    const dim3 gg(HID / BN, MROWS / BM);   // (16, 32)
    gemm_tn<<<gg, 256>>>(x, Wq, bq, nullptr, nullptr, 0, 1);   // -> g_q
    gemm_tn<<<gg, 256>>>(x, Wk, bk, nullptr, nullptr, 0, 2);   // -> g_k
    gemm_tn<<<gg, 256>>>(x, Wv, bv, nullptr, nullptr, 0, 3);   // -> g_v

    cudaFuncSetAttribute(flash_attn, cudaFuncAttributeMaxDynamicSharedMemorySize, ATTN_SMEM_BYTES);
    flash_attn<<<dim3(SEQ / AQ, NHEADS, BATCH), 256, ATTN_SMEM_BYTES>>>(alibi);

    gemm_tn<<<gg, 256>>>(nullptr, Wd, bd, resid, out, 1, 0);   // g_ctx -> out
}

// round 10
// speedup vs baseline: 1.6168x; 1.6168x over previous
#include <cuda_runtime.h>
#include <cuda_bf16.h>
#include <cstdint>
#include <math.h>

#define HID    2048
#define NHEADS 16
#define HDIM   128
#define SEQ    2048
#define BATCH  2
#define MROWS  (BATCH*SEQ)   // 4096

// ---------------- scratch (static device globals; no allocations allowed) ----
__device__ float g_q  [(size_t)MROWS * HID];
__device__ float g_k  [(size_t)MROWS * HID];
__device__ float g_v  [(size_t)MROWS * HID];
__device__ float g_ctx[(size_t)MROWS * HID];

// ======================= small helpers ======================================
__device__ __forceinline__ uint32_t smem_u32(const void* p) {
    uint32_t a;
    asm("{ .reg .u64 t; cvta.to.shared.u64 t, %1; cvt.u32.u64 %0, t; }" : "=r"(a) : "l"(p));
    return a;
}
__device__ __forceinline__ void ldm_x4(uint32_t& r0, uint32_t& r1, uint32_t& r2, uint32_t& r3,
                                       uint32_t addr) {
    asm volatile("ldmatrix.sync.aligned.m8n8.x4.shared.b16 {%0,%1,%2,%3}, [%4];"
                 : "=r"(r0), "=r"(r1), "=r"(r2), "=r"(r3) : "r"(addr));
}
__device__ __forceinline__ void ldm_x2(uint32_t& r0, uint32_t& r1, uint32_t addr) {
    asm volatile("ldmatrix.sync.aligned.m8n8.x2.shared.b16 {%0,%1}, [%2];"
                 : "=r"(r0), "=r"(r1) : "r"(addr));
}
__device__ __forceinline__ void mma16816(float* d, const uint32_t* a, const uint32_t* b) {
    asm volatile("mma.sync.aligned.m16n8k16.row.col.f32.bf16.bf16.f32 "
                 "{%0,%1,%2,%3}, {%4,%5,%6,%7}, {%8,%9}, {%0,%1,%2,%3};"
                 : "+f"(d[0]), "+f"(d[1]), "+f"(d[2]), "+f"(d[3])
                 : "r"(a[0]), "r"(a[1]), "r"(a[2]), "r"(a[3]), "r"(b[0]), "r"(b[1]));
}

// ======================= mma.sync bf16-split GEMM ===========================
// C[M,N] = A[M,K] @ W[N,K]^T + bias (+res).  M=MROWS, N=K=HID (compile-time).
// CTA 128x128, k-tile 32 fp32 -> hi/lo bf16 smem tiles, stride 40 bf16 (80B).
#define NKT        (HID/32)        // 64 k-tiles
#define TSTRIDE    40              // bf16 elems per smem row
#define TILE_B     (128*TSTRIDE*2) // 10240 bytes per tile
#define STAGE_B    (4*TILE_B)      // A_hi A_lo B_hi B_lo = 40960
#define GEMM_SMEM  (2*STAGE_B)     // 81920

__device__ __forceinline__ void cvt_pair(float4 v, uint2& hi, uint2& lo) {
    __nv_bfloat162 h01 = __float22bfloat162_rn(make_float2(v.x, v.y));
    __nv_bfloat162 h23 = __float22bfloat162_rn(make_float2(v.z, v.w));
    float2 f01 = __bfloat1622float2(h01);
    float2 f23 = __bfloat1622float2(h23);
    __nv_bfloat162 l01 = __float22bfloat162_rn(make_float2(v.x - f01.x, v.y - f01.y));
    __nv_bfloat162 l23 = __float22bfloat162_rn(make_float2(v.z - f23.x, v.w - f23.y));
    hi.x = *(uint32_t*)&h01; hi.y = *(uint32_t*)&h23;
    lo.x = *(uint32_t*)&l01; lo.y = *(uint32_t*)&l23;
}

__global__ __launch_bounds__(256)
void gemm_mma(const float* __restrict__ Ain, const float* __restrict__ W,
              const float* __restrict__ bias, const float* __restrict__ res,
              float* __restrict__ Cout, int a_sel, int c_sel)
{
    extern __shared__ char smem[];
    const float* A = (a_sel == 1) ? g_ctx : Ain;
    float*       C = (c_sel == 1) ? g_q
                   : (c_sel == 2) ? g_k
                   : (c_sel == 3) ? g_v : Cout;

    const int tid = threadIdx.x;
    const int wid = tid >> 5;
    const int ln  = tid & 31;
    const int wm  = wid >> 2;        // 0..1 : 64 rows
    const int wn  = wid & 3;         // 0..3 : 32 cols
    const int bm  = blockIdx.y * 128;
    const int bn  = blockIdx.x * 128;
    const uint32_t sb = smem_u32(smem);

    // per-thread ldmatrix base offsets (bytes, within a tile)
    const uint32_t aoff = ((wm * 64 + (ln & 15)) * TSTRIDE + (ln >> 4) * 8) * 2;
    const uint32_t boff = ((wn * 32 + (ln & 7)) * TSTRIDE + (((ln >> 3) & 1) * 8)) * 2;

    // global load indices: 4 float4 each for A and B
    const int r0 = tid >> 3;            // 0..31 row group base
    const int c4 = (tid & 7) * 4;       // k offset

    float acc[4][4][4];
#pragma unroll
    for (int i = 0; i < 4; i++)
#pragma unroll
        for (int j = 0; j < 4; j++)
#pragma unroll
            for (int t = 0; t < 4; t++) acc[i][j][t] = 0.f;

    float4 pa[4], pb[4];
    // preload k-tile 0
#pragma unroll
    for (int j = 0; j < 4; j++) {
        pa[j] = *(const float4*)(A + (size_t)(bm + r0 + j * 32) * HID + c4);
        pb[j] = *(const float4*)(W + (size_t)(bn + r0 + j * 32) * HID + c4);
    }
    {
        char* st = smem;
#pragma unroll
        for (int j = 0; j < 4; j++) {
            const uint32_t o = ((r0 + j * 32) * TSTRIDE + c4) * 2;
            uint2 hi, lo;
            cvt_pair(pa[j], hi, lo);
            *(uint2*)(st + o) = hi;
            *(uint2*)(st + TILE_B + o) = lo;
            cvt_pair(pb[j], hi, lo);
            *(uint2*)(st + 2 * TILE_B + o) = hi;
            *(uint2*)(st + 3 * TILE_B + o) = lo;
        }
    }
    __syncthreads();

    for (int kt = 0; kt < NKT; kt++) {
        const int s = kt & 1;
        if (kt + 1 < NKT) {
#pragma unroll
            for (int j = 0; j < 4; j++) {
                pa[j] = *(const float4*)(A + (size_t)(bm + r0 + j * 32) * HID + (kt + 1) * 32 + c4);
                pb[j] = *(const float4*)(W + (size_t)(bn + r0 + j * 32) * HID + (kt + 1) * 32 + c4);
            }
        }

        const uint32_t sa_hi = sb + s * STAGE_B;
        const uint32_t sa_lo = sa_hi + TILE_B;
        const uint32_t sbh   = sa_hi + 2 * TILE_B;
        const uint32_t sbl   = sa_hi + 3 * TILE_B;

#pragma unroll
        for (int ks = 0; ks < 2; ks++) {
            const uint32_t kb = ks * 32;   // 16 cols * 2B
            uint32_t ah[4][4], al[4][4], bh[4][2], bl[4][2];
#pragma unroll
            for (int mt = 0; mt < 4; mt++)
                ldm_x4(ah[mt][0], ah[mt][1], ah[mt][2], ah[mt][3],
                       sa_hi + aoff + mt * (16 * TSTRIDE * 2) + kb);
#pragma unroll
            for (int nt = 0; nt < 4; nt++)
                ldm_x2(bh[nt][0], bh[nt][1],
                       sbh + boff + nt * (8 * TSTRIDE * 2) + kb);
#pragma unroll
            for (int mt = 0; mt < 4; mt++)
#pragma unroll
                for (int nt = 0; nt < 4; nt++)
                    mma16816(acc[mt][nt], ah[mt], bh[nt]);

#pragma unroll
            for (int nt = 0; nt < 4; nt++)
                ldm_x2(bl[nt][0], bl[nt][1],
                       sbl + boff + nt * (8 * TSTRIDE * 2) + kb);
#pragma unroll
            for (int mt = 0; mt < 4; mt++)
#pragma unroll
                for (int nt = 0; nt < 4; nt++)
                    mma16816(acc[mt][nt], ah[mt], bl[nt]);

#pragma unroll
            for (int mt = 0; mt < 4; mt++)
                ldm_x4(al[mt][0], al[mt][1], al[mt][2], al[mt][3],
                       sa_lo + aoff + mt * (16 * TSTRIDE * 2) + kb);
#pragma unroll
            for (int mt = 0; mt < 4; mt++)
#pragma unroll
                for (int nt = 0; nt < 4; nt++)
                    mma16816(acc[mt][nt], al[mt], bh[nt]);
        }

        if (kt + 1 < NKT) {
            char* st = smem + (s ^ 1) * STAGE_B;
#pragma unroll
            for (int j = 0; j < 4; j++) {
                const uint32_t o = ((r0 + j * 32) * TSTRIDE + c4) * 2;
                uint2 hi, lo;
                cvt_pair(pa[j], hi, lo);
                *(uint2*)(st + o) = hi;
                *(uint2*)(st + TILE_B + o) = lo;
                cvt_pair(pb[j], hi, lo);
                *(uint2*)(st + 2 * TILE_B + o) = hi;
                *(uint2*)(st + 3 * TILE_B + o) = lo;
            }
        }
        __syncthreads();
    }

    // epilogue: direct gmem writes (float2), + bias (+res)
    const int grp = ln >> 2;
    const int tig = ln & 3;
#pragma unroll
    for (int mt = 0; mt < 4; mt++) {
#pragma unroll
        for (int nt = 0; nt < 4; nt++) {
            const int col  = bn + wn * 32 + nt * 8 + tig * 2;
            const int rowa = bm + wm * 64 + mt * 16 + grp;
            const int rowb = rowa + 8;
            float2 bv = *(const float2*)(bias + col);
            float2 o0, o1;
            o0.x = acc[mt][nt][0] + bv.x;  o0.y = acc[mt][nt][1] + bv.y;
            o1.x = acc[mt][nt][2] + bv.x;  o1.y = acc[mt][nt][3] + bv.y;
            if (res) {
                float2 ra = *(const float2*)(res + (size_t)rowa * HID + col);
                float2 rb = *(const float2*)(res + (size_t)rowb * HID + col);
                o0.x += ra.x; o0.y += ra.y;
                o1.x += rb.x; o1.y += rb.y;
            }
            *(float2*)(C + (size_t)rowa * HID + col) = o0;
            *(float2*)(C + (size_t)rowb * HID + col) = o1;
        }
    }
}

// ---------------- Flash attention (unchanged from R3 pass) ------------------
#define AQ 64
#define AK 64
#define KPAD (AK + 4)    // 68

#define ATTN_SMEM_FLOATS (AQ*HDIM + HDIM*KPAD + AK*HDIM + AQ*KPAD)
#define ATTN_SMEM_BYTES  (ATTN_SMEM_FLOATS * 4)

__global__ __launch_bounds__(256)
void flash_attn(const float* __restrict__ alibi)
{
    extern __shared__ float sm[];
    float* qs  = sm;                      // [AQ][HDIM]
    float* kst = qs  + AQ * HDIM;         // [HDIM][KPAD]  (K transposed)
    float* vs  = kst + HDIM * KPAD;       // [AK][HDIM]
    float* ps  = vs  + AK * HDIM;         // [AQ][KPAD]

    const int qb  = blockIdx.x;
    const int h   = blockIdx.y;
    const int b   = blockIdx.z;
    const int tid = threadIdx.x;
    const int ty  = tid >> 4;
    const int tx  = tid & 15;

    const float inv_norm = 0.08838834764831844f;  // 1/sqrt(128)

    for (int i = tid; i < AQ * (HDIM / 4); i += 256) {
        const int r  = i / (HDIM / 4);
        const int c4 = (i % (HDIM / 4)) * 4;
        float4 v = *(const float4*)(g_q + (size_t)(b * SEQ + qb * AQ + r) * HID + h * HDIM + c4);
        *(float4*)(qs + r * HDIM + c4) = v;
    }

    float m[4], l[4];
    float acc[4][8];
#pragma unroll
    for (int i = 0; i < 4; i++) { m[i] = -INFINITY; l[i] = 0.f; }
#pragma unroll
    for (int i = 0; i < 4; i++)
#pragma unroll
        for (int j = 0; j < 8; j++) acc[i][j] = 0.f;

    const float* al = alibi + (size_t)(b * NHEADS + h) * SEQ;

    for (int kt = 0; kt < SEQ; kt += AK) {
        __syncthreads();
        for (int i = tid; i < AK * (HDIM / 4); i += 256) {
            const int r  = i / (HDIM / 4);
            const int c4 = (i % (HDIM / 4)) * 4;
            float4 v = *(const float4*)(g_k + (size_t)(b * SEQ + kt + r) * HID + h * HDIM + c4);
            kst[(c4 + 0) * KPAD + r] = v.x;
            kst[(c4 + 1) * KPAD + r] = v.y;
            kst[(c4 + 2) * KPAD + r] = v.z;
            kst[(c4 + 3) * KPAD + r] = v.w;
        }
        for (int i = tid; i < AK * (HDIM / 4); i += 256) {
            const int r  = i / (HDIM / 4);
            const int c4 = (i % (HDIM / 4)) * 4;
            float4 v = *(const float4*)(g_v + (size_t)(b * SEQ + kt + r) * HID + h * HDIM + c4);
            *(float4*)(vs + r * HDIM + c4) = v;
        }
        __syncthreads();

        float s[4][4];
#pragma unroll
        for (int i = 0; i < 4; i++)
#pragma unroll
            for (int j = 0; j < 4; j++) s[i][j] = 0.f;

#pragma unroll 4
        for (int kk = 0; kk < HDIM; kk++) {
            float a[4], bb[4];
#pragma unroll
            for (int i = 0; i < 4; i++) a[i]  = qs[(ty * 4 + i) * HDIM + kk];
#pragma unroll
            for (int j = 0; j < 4; j++) bb[j] = kst[kk * KPAD + tx * 4 + j];
#pragma unroll
            for (int i = 0; i < 4; i++)
#pragma unroll
                for (int j = 0; j < 4; j++)
                    s[i][j] = fmaf(a[i], bb[j], s[i][j]);
        }

        float alv[4];
#pragma unroll
        for (int j = 0; j < 4; j++) alv[j] = al[kt + tx * 4 + j];
#pragma unroll
        for (int i = 0; i < 4; i++)
#pragma unroll
            for (int j = 0; j < 4; j++)
                s[i][j] = s[i][j] * inv_norm + alv[j];

        float rowscale[4];
#pragma unroll
        for (int i = 0; i < 4; i++) {
            float rm = s[i][0];
#pragma unroll
            for (int j = 1; j < 4; j++) rm = fmaxf(rm, s[i][j]);
#pragma unroll
            for (int off = 8; off >= 1; off >>= 1)
                rm = fmaxf(rm, __shfl_xor_sync(0xffffffffu, rm, off, 16));
            const float mnew = fmaxf(m[i], rm);
            rowscale[i] = __expf(m[i] - mnew);
            float rs = 0.f;
#pragma unroll
            for (int j = 0; j < 4; j++) {
                const float p = __expf(s[i][j] - mnew);
                s[i][j] = p;
                rs += p;
            }
#pragma unroll
            for (int off = 8; off >= 1; off >>= 1)
                rs += __shfl_xor_sync(0xffffffffu, rs, off, 16);
            l[i] = l[i] * rowscale[i] + rs;
            m[i] = mnew;
        }

#pragma unroll
        for (int i = 0; i < 4; i++)
#pragma unroll
            for (int j = 0; j < 4; j++)
                ps[(ty * 4 + i) * KPAD + tx * 4 + j] = s[i][j];
        __syncthreads();

#pragma unroll
        for (int i = 0; i < 4; i++)
#pragma unroll
            for (int j = 0; j < 8; j++) acc[i][j] *= rowscale[i];

#pragma unroll 4
        for (int c = 0; c < AK; c++) {
            float pv[4], vv[8];
#pragma unroll
            for (int i = 0; i < 4; i++) pv[i] = ps[(ty * 4 + i) * KPAD + c];
#pragma unroll
            for (int j = 0; j < 8; j++) vv[j] = vs[c * HDIM + tx * 8 + j];
#pragma unroll
            for (int i = 0; i < 4; i++)
#pragma unroll
                for (int j = 0; j < 8; j++)
                    acc[i][j] = fmaf(pv[i], vv[j], acc[i][j]);
        }
    }

#pragma unroll
    for (int i = 0; i < 4; i++) {
        const float inv_l = 1.0f / l[i];
        const size_t base = (size_t)(b * SEQ + qb * AQ + ty * 4 + i) * HID + h * HDIM + tx * 8;
#pragma unroll
        for (int j = 0; j < 8; j++)
            g_ctx[base + j] = acc[i][j] * inv_l;
    }
}

// ---------------- launch ----------------------------------------------------
extern "C" void kernel_launch(void* const* d_in, const int* in_sizes, int n_in,
                              void* d_out, int out_size)
{
    const float* x     = (const float*)d_in[0];
    const float* resid = (const float*)d_in[1];
    const float* alibi = (const float*)d_in[2];
    const float* Wq    = (const float*)d_in[3];
    const float* bq    = (const float*)d_in[4];
    const float* Wk    = (const float*)d_in[5];
    const float* bk    = (const float*)d_in[6];
    const float* Wv    = (const float*)d_in[7];
    const float* bv    = (const float*)d_in[8];
    const float* Wd    = (const float*)d_in[9];
    const float* bd    = (const float*)d_in[10];
    float* out = (float*)d_out;

    cudaFuncSetAttribute(gemm_mma, cudaFuncAttributeMaxDynamicSharedMemorySize, GEMM_SMEM);
    cudaFuncSetAttribute(flash_attn, cudaFuncAttributeMaxDynamicSharedMemorySize, ATTN_SMEM_BYTES);

    const dim3 gg(HID / 128, MROWS / 128);   // (16, 32)
    gemm_mma<<<gg, 256, GEMM_SMEM>>>(x, Wq, bq, nullptr, nullptr, 0, 1);   // -> g_q
    gemm_mma<<<gg, 256, GEMM_SMEM>>>(x, Wk, bk, nullptr, nullptr, 0, 2);   // -> g_k
    gemm_mma<<<gg, 256, GEMM_SMEM>>>(x, Wv, bv, nullptr, nullptr, 0, 3);   // -> g_v

    flash_attn<<<dim3(SEQ / AQ, NHEADS, BATCH), 256, ATTN_SMEM_BYTES>>>(alibi);

    gemm_mma<<<gg, 256, GEMM_SMEM>>>(nullptr, Wd, bd, resid, out, 1, 0);   // g_ctx -> out
}

// round 16
// speedup vs baseline: 3.2865x; 2.0327x over previous
#include <cuda_runtime.h>
#include <cuda_bf16.h>
#include <cstdint>
#include <math.h>

#define HID    2048
#define NHEADS 16
#define HDIM   128
#define SEQ    2048
#define BATCH  2
#define MROWS  (BATCH*SEQ)   // 4096

// ---------------- scratch (static device globals; no allocations allowed) ----
__device__ float g_q  [(size_t)MROWS * HID];
__device__ float g_k  [(size_t)MROWS * HID];
__device__ float g_v  [(size_t)MROWS * HID];
__device__ float g_ctx[(size_t)MROWS * HID];

// ======================= small helpers ======================================
__device__ __forceinline__ uint32_t smem_u32(const void* p) {
    uint32_t a;
    asm("{ .reg .u64 t; cvta.to.shared.u64 t, %1; cvt.u32.u64 %0, t; }" : "=r"(a) : "l"(p));
    return a;
}
__device__ __forceinline__ void ldm_x4(uint32_t& r0, uint32_t& r1, uint32_t& r2, uint32_t& r3,
                                       uint32_t addr) {
    asm volatile("ldmatrix.sync.aligned.m8n8.x4.shared.b16 {%0,%1,%2,%3}, [%4];"
                 : "=r"(r0), "=r"(r1), "=r"(r2), "=r"(r3) : "r"(addr));
}
__device__ __forceinline__ void ldm_x2(uint32_t& r0, uint32_t& r1, uint32_t addr) {
    asm volatile("ldmatrix.sync.aligned.m8n8.x2.shared.b16 {%0,%1}, [%2];"
                 : "=r"(r0), "=r"(r1) : "r"(addr));
}
__device__ __forceinline__ void ldm_x2t(uint32_t& r0, uint32_t& r1, uint32_t addr) {
    asm volatile("ldmatrix.sync.aligned.m8n8.x2.trans.shared.b16 {%0,%1}, [%2];"
                 : "=r"(r0), "=r"(r1) : "r"(addr));
}
__device__ __forceinline__ void mma16816(float* d, const uint32_t* a, const uint32_t* b) {
    asm volatile("mma.sync.aligned.m16n8k16.row.col.f32.bf16.bf16.f32 "
                 "{%0,%1,%2,%3}, {%4,%5,%6,%7}, {%8,%9}, {%0,%1,%2,%3};"
                 : "+f"(d[0]), "+f"(d[1]), "+f"(d[2]), "+f"(d[3])
                 : "r"(a[0]), "r"(a[1]), "r"(a[2]), "r"(a[3]), "r"(b[0]), "r"(b[1]));
}
__device__ __forceinline__ void cvt_pair(float4 v, uint2& hi, uint2& lo) {
    __nv_bfloat162 h01 = __float22bfloat162_rn(make_float2(v.x, v.y));
    __nv_bfloat162 h23 = __float22bfloat162_rn(make_float2(v.z, v.w));
    float2 f01 = __bfloat1622float2(h01);
    float2 f23 = __bfloat1622float2(h23);
    __nv_bfloat162 l01 = __float22bfloat162_rn(make_float2(v.x - f01.x, v.y - f01.y));
    __nv_bfloat162 l23 = __float22bfloat162_rn(make_float2(v.z - f23.x, v.w - f23.y));
    hi.x = *(uint32_t*)&h01; hi.y = *(uint32_t*)&h23;
    lo.x = *(uint32_t*)&l01; lo.y = *(uint32_t*)&l23;
}
__device__ __forceinline__ void pack_hl(float x, float y, uint32_t& hi, uint32_t& lo) {
    __nv_bfloat162 h = __float22bfloat162_rn(make_float2(x, y));
    float2 hf = __bfloat1622float2(h);
    __nv_bfloat162 l = __float22bfloat162_rn(make_float2(x - hf.x, y - hf.y));
    hi = *(uint32_t*)&h; lo = *(uint32_t*)&l;
}

// ======================= mma.sync bf16-split GEMM (UNCHANGED, proven R10) ===
#define NKT        (HID/32)
#define TSTRIDE    40
#define TILE_B     (128*TSTRIDE*2)
#define STAGE_B    (4*TILE_B)
#define GEMM_SMEM  (2*STAGE_B)

__global__ __launch_bounds__(256)
void gemm_mma(const float* __restrict__ Ain, const float* __restrict__ W,
              const float* __restrict__ bias, const float* __restrict__ res,
              float* __restrict__ Cout, int a_sel, int c_sel)
{
    extern __shared__ char smem[];
    const float* A = (a_sel == 1) ? g_ctx : Ain;
    float*       C = (c_sel == 1) ? g_q
                   : (c_sel == 2) ? g_k
                   : (c_sel == 3) ? g_v : Cout;

    const int tid = threadIdx.x;
    const int wid = tid >> 5;
    const int ln  = tid & 31;
    const int wm  = wid >> 2;
    const int wn  = wid & 3;
    const int bm  = blockIdx.y * 128;
    const int bn  = blockIdx.x * 128;
    const uint32_t sb = smem_u32(smem);

    const uint32_t aoff = ((wm * 64 + (ln & 15)) * TSTRIDE + (ln >> 4) * 8) * 2;
    const uint32_t boff = ((wn * 32 + (ln & 7)) * TSTRIDE + (((ln >> 3) & 1) * 8)) * 2;

    const int r0 = tid >> 3;
    const int c4 = (tid & 7) * 4;

    float acc[4][4][4];
#pragma unroll
    for (int i = 0; i < 4; i++)
#pragma unroll
        for (int j = 0; j < 4; j++)
#pragma unroll
            for (int t = 0; t < 4; t++) acc[i][j][t] = 0.f;

    float4 pa[4], pb[4];
#pragma unroll
    for (int j = 0; j < 4; j++) {
        pa[j] = *(const float4*)(A + (size_t)(bm + r0 + j * 32) * HID + c4);
        pb[j] = *(const float4*)(W + (size_t)(bn + r0 + j * 32) * HID + c4);
    }
    {
        char* st = smem;
#pragma unroll
        for (int j = 0; j < 4; j++) {
            const uint32_t o = ((r0 + j * 32) * TSTRIDE + c4) * 2;
            uint2 hi, lo;
            cvt_pair(pa[j], hi, lo);
            *(uint2*)(st + o) = hi;
            *(uint2*)(st + TILE_B + o) = lo;
            cvt_pair(pb[j], hi, lo);
            *(uint2*)(st + 2 * TILE_B + o) = hi;
            *(uint2*)(st + 3 * TILE_B + o) = lo;
        }
    }
    __syncthreads();

    for (int kt = 0; kt < NKT; kt++) {
        const int s = kt & 1;
        if (kt + 1 < NKT) {
#pragma unroll
            for (int j = 0; j < 4; j++) {
                pa[j] = *(const float4*)(A + (size_t)(bm + r0 + j * 32) * HID + (kt + 1) * 32 + c4);
                pb[j] = *(const float4*)(W + (size_t)(bn + r0 + j * 32) * HID + (kt + 1) * 32 + c4);
            }
        }

        const uint32_t sa_hi = sb + s * STAGE_B;
        const uint32_t sa_lo = sa_hi + TILE_B;
        const uint32_t sbh   = sa_hi + 2 * TILE_B;
        const uint32_t sbl   = sa_hi + 3 * TILE_B;

#pragma unroll
        for (int ks = 0; ks < 2; ks++) {
            const uint32_t kb = ks * 32;
            uint32_t ah[4][4], al[4][4], bh[4][2], bl[4][2];
#pragma unroll
            for (int mt = 0; mt < 4; mt++)
                ldm_x4(ah[mt][0], ah[mt][1], ah[mt][2], ah[mt][3],
                       sa_hi + aoff + mt * (16 * TSTRIDE * 2) + kb);
#pragma unroll
            for (int nt = 0; nt < 4; nt++)
                ldm_x2(bh[nt][0], bh[nt][1],
                       sbh + boff + nt * (8 * TSTRIDE * 2) + kb);
#pragma unroll
            for (int mt = 0; mt < 4; mt++)
#pragma unroll
                for (int nt = 0; nt < 4; nt++)
                    mma16816(acc[mt][nt], ah[mt], bh[nt]);

#pragma unroll
            for (int nt = 0; nt < 4; nt++)
                ldm_x2(bl[nt][0], bl[nt][1],
                       sbl + boff + nt * (8 * TSTRIDE * 2) + kb);
#pragma unroll
            for (int mt = 0; mt < 4; mt++)
#pragma unroll
                for (int nt = 0; nt < 4; nt++)
                    mma16816(acc[mt][nt], ah[mt], bl[nt]);

#pragma unroll
            for (int mt = 0; mt < 4; mt++)
                ldm_x4(al[mt][0], al[mt][1], al[mt][2], al[mt][3],
                       sa_lo + aoff + mt * (16 * TSTRIDE * 2) + kb);
#pragma unroll
            for (int mt = 0; mt < 4; mt++)
#pragma unroll
                for (int nt = 0; nt < 4; nt++)
                    mma16816(acc[mt][nt], al[mt], bh[nt]);
        }

        if (kt + 1 < NKT) {
            char* st = smem + (s ^ 1) * STAGE_B;
#pragma unroll
            for (int j = 0; j < 4; j++) {
                const uint32_t o = ((r0 + j * 32) * TSTRIDE + c4) * 2;
                uint2 hi, lo;
                cvt_pair(pa[j], hi, lo);
                *(uint2*)(st + o) = hi;
                *(uint2*)(st + TILE_B + o) = lo;
                cvt_pair(pb[j], hi, lo);
                *(uint2*)(st + 2 * TILE_B + o) = hi;
                *(uint2*)(st + 3 * TILE_B + o) = lo;
            }
        }
        __syncthreads();
    }

    const int grp = ln >> 2;
    const int tig = ln & 3;
#pragma unroll
    for (int mt = 0; mt < 4; mt++) {
#pragma unroll
        for (int nt = 0; nt < 4; nt++) {
            const int col  = bn + wn * 32 + nt * 8 + tig * 2;
            const int rowa = bm + wm * 64 + mt * 16 + grp;
            const int rowb = rowa + 8;
            float2 bv = *(const float2*)(bias + col);
            float2 o0, o1;
            o0.x = acc[mt][nt][0] + bv.x;  o0.y = acc[mt][nt][1] + bv.y;
            o1.x = acc[mt][nt][2] + bv.x;  o1.y = acc[mt][nt][3] + bv.y;
            if (res) {
                float2 ra = *(const float2*)(res + (size_t)rowa * HID + col);
                float2 rb = *(const float2*)(res + (size_t)rowb * HID + col);
                o0.x += ra.x; o0.y += ra.y;
                o1.x += rb.x; o1.y += rb.y;
            }
            *(float2*)(C + (size_t)rowa * HID + col) = o0;
            *(float2*)(C + (size_t)rowb * HID + col) = o1;
        }
    }
}

// ======================= mma.sync bf16-split flash attention ================
// CTA: 256 thr (8 warps), Q tile 128 rows (16 per warp), KV tile 64.
// smem: [0,8K) alibi fp32; stage: Kh,Kl,Vh,Vl each 64x(128+8) bf16 (17408B).
// Q staged through the stage area once, then held as register fragments.
#define QTILE  128
#define KTILE  64
#define KSTR   136                    // bf16 elems per row (128 + 8 pad)
#define AB_OFF 0
#define ST_OFF 8192
#define KTB    (KTILE*KSTR*2)         // 17408
#define KH_OFF (ST_OFF)
#define KL_OFF (KH_OFF + KTB)
#define VH_OFF (KL_OFF + KTB)
#define VL_OFF (VH_OFF + KTB)
#define ATTN_SMEM (VL_OFF + KTB)      // 8192 + 4*17408 = 77824
#define QSTG   (QTILE*KSTR*2)         // 34816 (x2 fits in 4*KTB)

__global__ __launch_bounds__(256)
void flash_attn_mma(const float* __restrict__ alibi)
{
    extern __shared__ char smem[];
    const uint32_t sb = smem_u32(smem);
    const int tid = threadIdx.x;
    const int wid = tid >> 5;
    const int ln  = tid & 31;
    const int h = blockIdx.y;
    const int b = blockIdx.z;
    const int qbase = blockIdx.x * QTILE;
    const float inv_norm = 0.08838834764831844f;

    // stage alibi row (2048 fp32)
    {
        const float* al = alibi + (size_t)(b * NHEADS + h) * SEQ;
        float* als = (float*)smem;
        for (int i = tid; i < SEQ / 4; i += 256)
            *(float4*)(als + i * 4) = *(const float4*)(al + i * 4);
    }
    // stage Q hi/lo into stage area
    {
        char* qh = smem + ST_OFF;
        char* ql = qh + QSTG;
#pragma unroll
        for (int i = 0; i < 16; i++) {
            const int idx = tid + i * 256;
            const int r  = idx >> 5;
            const int c4 = (idx & 31) * 4;
            float4 v = *(const float4*)(g_q + (size_t)(b * SEQ + qbase + r) * HID + h * HDIM + c4);
            uint2 hi, lo;
            cvt_pair(v, hi, lo);
            *(uint2*)(qh + (r * KSTR + c4) * 2) = hi;
            *(uint2*)(ql + (r * KSTR + c4) * 2) = lo;
        }
    }
    __syncthreads();

    // Q fragments (m16 x k128 per warp), hi and lo
    uint32_t qfh[8][4], qfl[8][4];
    {
        const uint32_t aoff = sb + ST_OFF + ((wid * 16 + (ln & 15)) * KSTR + (ln >> 4) * 8) * 2;
#pragma unroll
        for (int ks = 0; ks < 8; ks++) {
            ldm_x4(qfh[ks][0], qfh[ks][1], qfh[ks][2], qfh[ks][3], aoff + ks * 32);
            ldm_x4(qfl[ks][0], qfl[ks][1], qfl[ks][2], qfl[ks][3], aoff + QSTG + ks * 32);
        }
    }
    __syncthreads();   // Q staging free; stage now used for K/V

    float oacc[16][4];
#pragma unroll
    for (int nt = 0; nt < 16; nt++)
#pragma unroll
        for (int t = 0; t < 4; t++) oacc[nt][t] = 0.f;
    float mrow0 = -INFINITY, mrow1 = -INFINITY, lrow0 = 0.f, lrow1 = 0.f;

    const uint32_t kbo = sb + KH_OFF + ((ln & 7) * KSTR + ((ln >> 3) & 1) * 8) * 2;
    // V (row-major) trans-ldmatrix base: rows = kv (k2*16 + lane pattern), col = d tile
    const uint32_t vbo = sb + VH_OFF + (((ln & 7) + ((ln >> 3) & 1) * 8) * KSTR) * 2;
    const float* als = (const float*)smem;

    for (int kt = 0; kt < SEQ / KTILE; kt++) {
        // load + convert K,V tiles (64 x 128 fp32 each)
        {
            char* kh = smem + KH_OFF;
            char* kl = smem + KL_OFF;
            char* vh = smem + VH_OFF;
            char* vl = smem + VL_OFF;
#pragma unroll
            for (int i = 0; i < 8; i++) {
                const int idx = tid + i * 256;
                const int r  = idx >> 5;
                const int c4 = (idx & 31) * 4;
                const size_t g = (size_t)(b * SEQ + kt * KTILE + r) * HID + h * HDIM + c4;
                const uint32_t o = (r * KSTR + c4) * 2;
                uint2 hi, lo;
                float4 kv4 = *(const float4*)(g_k + g);
                cvt_pair(kv4, hi, lo);
                *(uint2*)(kh + o) = hi;
                *(uint2*)(kl + o) = lo;
                float4 vv4 = *(const float4*)(g_v + g);
                cvt_pair(vv4, hi, lo);
                *(uint2*)(vh + o) = hi;
                *(uint2*)(vl + o) = lo;
            }
        }
        __syncthreads();

        // ---- S = Q @ K^T (3-mma split) ----
        float s[8][4];
#pragma unroll
        for (int nt = 0; nt < 8; nt++)
#pragma unroll
            for (int t = 0; t < 4; t++) s[nt][t] = 0.f;

#pragma unroll
        for (int nt = 0; nt < 8; nt++) {
            const uint32_t kb_nt = kbo + nt * (8 * KSTR * 2);
#pragma unroll
            for (int ks = 0; ks < 8; ks++) {
                uint32_t bh[2], bl[2];
                ldm_x2(bh[0], bh[1], kb_nt + ks * 32);
                ldm_x2(bl[0], bl[1], kb_nt + KTB + ks * 32);
                mma16816(s[nt], qfh[ks], bh);
                mma16816(s[nt], qfh[ks], bl);
                mma16816(s[nt], qfl[ks], bh);
            }
        }

        // ---- online softmax (rows r0 = ln>>2, r1 = r0+8) ----
        const int cbase = kt * KTILE + (ln & 3) * 2;
        float mx0 = -INFINITY, mx1 = -INFINITY;
#pragma unroll
        for (int nt = 0; nt < 8; nt++) {
            const float a0 = als[cbase + nt * 8];
            const float a1 = als[cbase + nt * 8 + 1];
            s[nt][0] = s[nt][0] * inv_norm + a0;
            s[nt][1] = s[nt][1] * inv_norm + a1;
            s[nt][2] = s[nt][2] * inv_norm + a0;
            s[nt][3] = s[nt][3] * inv_norm + a1;
            mx0 = fmaxf(mx0, fmaxf(s[nt][0], s[nt][1]));
            mx1 = fmaxf(mx1, fmaxf(s[nt][2], s[nt][3]));
        }
        mx0 = fmaxf(mx0, __shfl_xor_sync(0xffffffffu, mx0, 1));
        mx0 = fmaxf(mx0, __shfl_xor_sync(0xffffffffu, mx0, 2));
        mx1 = fmaxf(mx1, __shfl_xor_sync(0xffffffffu, mx1, 1));
        mx1 = fmaxf(mx1, __shfl_xor_sync(0xffffffffu, mx1, 2));
        const float mn0 = fmaxf(mrow0, mx0);
        const float mn1 = fmaxf(mrow1, mx1);
        const float sc0 = __expf(mrow0 - mn0);
        const float sc1 = __expf(mrow1 - mn1);
        mrow0 = mn0; mrow1 = mn1;
        float sum0 = 0.f, sum1 = 0.f;
#pragma unroll
        for (int nt = 0; nt < 8; nt++) {
            s[nt][0] = __expf(s[nt][0] - mn0);
            s[nt][1] = __expf(s[nt][1] - mn0);
            s[nt][2] = __expf(s[nt][2] - mn1);
            s[nt][3] = __expf(s[nt][3] - mn1);
            sum0 += s[nt][0] + s[nt][1];
            sum1 += s[nt][2] + s[nt][3];
        }
        sum0 += __shfl_xor_sync(0xffffffffu, sum0, 1);
        sum0 += __shfl_xor_sync(0xffffffffu, sum0, 2);
        sum1 += __shfl_xor_sync(0xffffffffu, sum1, 1);
        sum1 += __shfl_xor_sync(0xffffffffu, sum1, 2);
        lrow0 = lrow0 * sc0 + sum0;
        lrow1 = lrow1 * sc1 + sum1;
#pragma unroll
        for (int nt = 0; nt < 16; nt++) {
            oacc[nt][0] *= sc0; oacc[nt][1] *= sc0;
            oacc[nt][2] *= sc1; oacc[nt][3] *= sc1;
        }

        // ---- pack P fragments (C-frag -> A-frag identity), hi/lo ----
        uint32_t ph[4][4], pl[4][4];
#pragma unroll
        for (int k2 = 0; k2 < 4; k2++) {
            pack_hl(s[2*k2][0],   s[2*k2][1],   ph[k2][0], pl[k2][0]);
            pack_hl(s[2*k2][2],   s[2*k2][3],   ph[k2][1], pl[k2][1]);
            pack_hl(s[2*k2+1][0], s[2*k2+1][1], ph[k2][2], pl[k2][2]);
            pack_hl(s[2*k2+1][2], s[2*k2+1][3], ph[k2][3], pl[k2][3]);
        }

        // ---- O += P @ V (V row-major, ldmatrix.trans for B operand) ----
#pragma unroll
        for (int nt = 0; nt < 16; nt++) {
            const uint32_t vb_nt = vbo + nt * 16;   // d offset: nt*8 elems *2B
#pragma unroll
            for (int k2 = 0; k2 < 4; k2++) {
                uint32_t bh[2], bl[2];
                const uint32_t ra = vb_nt + k2 * (16 * KSTR * 2);  // kv row block
                ldm_x2t(bh[0], bh[1], ra);
                ldm_x2t(bl[0], bl[1], ra + KTB);
                mma16816(oacc[nt], ph[k2], bh);
                mma16816(oacc[nt], ph[k2], bl);
                mma16816(oacc[nt], pl[k2], bh);
            }
        }
        __syncthreads();   // done reading stage
    }

    // epilogue
    const float inv0 = 1.f / lrow0;
    const float inv1 = 1.f / lrow1;
    const int row0 = b * SEQ + qbase + wid * 16 + (ln >> 2);
#pragma unroll
    for (int nt = 0; nt < 16; nt++) {
        const int col = h * HDIM + nt * 8 + (ln & 3) * 2;
        float2 o0, o1;
        o0.x = oacc[nt][0] * inv0; o0.y = oacc[nt][1] * inv0;
        o1.x = oacc[nt][2] * inv1; o1.y = oacc[nt][3] * inv1;
        *(float2*)(g_ctx + (size_t)row0 * HID + col) = o0;
        *(float2*)(g_ctx + (size_t)(row0 + 8) * HID + col) = o1;
    }
}

// ---------------- launch ----------------------------------------------------
extern "C" void kernel_launch(void* const* d_in, const int* in_sizes, int n_in,
                              void* d_out, int out_size)
{
    const float* x     = (const float*)d_in[0];
    const float* resid = (const float*)d_in[1];
    const float* alibi = (const float*)d_in[2];
    const float* Wq    = (const float*)d_in[3];
    const float* bq    = (const float*)d_in[4];
    const float* Wk    = (const float*)d_in[5];
    const float* bk    = (const float*)d_in[6];
    const float* Wv    = (const float*)d_in[7];
    const float* bv    = (const float*)d_in[8];
    const float* Wd    = (const float*)d_in[9];
    const float* bd    = (const float*)d_in[10];
    float* out = (float*)d_out;

    cudaFuncSetAttribute(gemm_mma, cudaFuncAttributeMaxDynamicSharedMemorySize, GEMM_SMEM);
    cudaFuncSetAttribute(flash_attn_mma, cudaFuncAttributeMaxDynamicSharedMemorySize, ATTN_SMEM);

    const dim3 gg(HID / 128, MROWS / 128);   // (16, 32)
    gemm_mma<<<gg, 256, GEMM_SMEM>>>(x, Wq, bq, nullptr, nullptr, 0, 1);   // -> g_q
    gemm_mma<<<gg, 256, GEMM_SMEM>>>(x, Wk, bk, nullptr, nullptr, 0, 2);   // -> g_k
    gemm_mma<<<gg, 256, GEMM_SMEM>>>(x, Wv, bv, nullptr, nullptr, 0, 3);   // -> g_v

    flash_attn_mma<<<dim3(SEQ / QTILE, NHEADS, BATCH), 256, ATTN_SMEM>>>(alibi);

    gemm_mma<<<gg, 256, GEMM_SMEM>>>(nullptr, Wd, bd, resid, out, 1, 0);   // g_ctx -> out
}